// round 10
// baseline (speedup 1.0000x reference)
#include <cuda_runtime.h>
#include <cuda_bf16.h>
#include <math.h>
#include <stdint.h>

#define N_ROWS 65536
#define DD 512
#define EE 256
#define TT 128
#define KK 5
#define KTOT 896

#define BM 32
#define BN 512
#define BK 32
#define NCH (KTOT / BK)     // 28
#define APADB 80            // bytes per k-row in smem tiles
#define XSTRIDE 520         // xbuf row stride in bf16 elems

// smem: A 2 x 2560 | B 2 x 40960 | red 512   (xbuf reuses [0, 33280))
#define SM_A0 0u
#define SM_A1 2560u
#define SM_B0 5120u
#define SM_B1 46080u
#define SM_RED 87040u
#define SMEM_TOTAL 87616u

// ---------------- device scratch ----------------
__device__ __align__(16) __nv_bfloat16 g_Wq_bf16[DD * KTOT];   // [512][896] K-major

__device__ __forceinline__ float clipf(float x, float lo, float hi) {
    return fminf(fmaxf(x, lo), hi);
}
__device__ __forceinline__ uint32_t sptr(const void* p) {
    return (uint32_t)__cvta_generic_to_shared(p);
}

__global__ void convert_wq(const float* __restrict__ Wq) {
    int i = blockIdx.x * blockDim.x + threadIdx.x;
    if (i < DD * KTOT) g_Wq_bf16[i] = __float2bfloat16(Wq[i]);
}

__device__ __forceinline__ void mma16816(float c[4], uint32_t a0, uint32_t a1,
                                         uint32_t a2, uint32_t a3,
                                         uint32_t b0, uint32_t b1) {
    asm volatile(
        "mma.sync.aligned.m16n8k16.row.col.f32.bf16.bf16.f32 "
        "{%0,%1,%2,%3}, {%4,%5,%6,%7}, {%8,%9}, {%0,%1,%2,%3};\n"
        : "+f"(c[0]), "+f"(c[1]), "+f"(c[2]), "+f"(c[3])
        : "r"(a0), "r"(a1), "r"(a2), "r"(a3), "r"(b0), "r"(b1));
}
__device__ __forceinline__ void ldsm4(uint32_t& r0, uint32_t& r1, uint32_t& r2,
                                      uint32_t& r3, uint32_t addr) {
    asm volatile("ldmatrix.sync.aligned.m8n8.x4.shared.b16 {%0,%1,%2,%3}, [%4];"
                 : "=r"(r0), "=r"(r1), "=r"(r2), "=r"(r3) : "r"(addr));
}

// block reduce over 256 threads (8 warps)
template <int M>
__device__ __forceinline__ void block_reduce256(float* v, float (*red)[16], int tid) {
    int lane = tid & 31, w = tid >> 5;
    #pragma unroll
    for (int off = 16; off > 0; off >>= 1)
        #pragma unroll
        for (int m = 0; m < M; m++)
            v[m] += __shfl_xor_sync(0xffffffffu, v[m], off);
    if (lane == 0)
        #pragma unroll
        for (int m = 0; m < M; m++) red[w][m] = v[m];
    __syncthreads();
    #pragma unroll
    for (int m = 0; m < M; m++) {
        float s = red[0][m];
        #pragma unroll
        for (int w2 = 1; w2 < 8; w2++) s += red[w2][m];
        v[m] = s;
    }
    __syncthreads();
}

// ---------------------------------------------------------------------------
// Fused 32x512x896 GEMM + row phase. 256 thr = 8 warps, 2 CTAs/SM for
// cross-CTA GEMM/epilogue overlap. Warp tile 32x64 (acc 64 regs).
// Epilogue: one row at a time across the CTA (thread owns 2 of 512 elems).
// ---------------------------------------------------------------------------
__global__ __launch_bounds__(256, 2) void fused_kernel(
    const float* __restrict__ raw,
    const float* __restrict__ edge,
    const float* __restrict__ timeenc,
    const float* __restrict__ proto,
    const float* __restrict__ bq,
    const float* __restrict__ Wg,
    const float* __restrict__ bg,
    const float* __restrict__ gamma,
    const float* __restrict__ beta,
    const float* __restrict__ temperature,
    float* __restrict__ out)
{
    extern __shared__ char smem[];
    const uint32_t sb = sptr(smem);
    const int tid  = threadIdx.x;
    const int lane = tid & 31;
    const int wid  = tid >> 5;
    const int n0   = blockIdx.x * BM;

    float acc[2][8][4];
    #pragma unroll
    for (int mt = 0; mt < 2; mt++)
        #pragma unroll
        for (int nt = 0; nt < 8; nt++)
            #pragma unroll
            for (int j = 0; j < 4; j++) acc[mt][nt][j] = 0.f;

    float4 areg;

    auto ldgA = [&](int c) {
        const int kt = c * BK;
        const float* src; int stride;
        if (kt < DD)            { src = raw     + (size_t)n0 * DD + kt;             stride = DD; }
        else if (kt < DD + EE)  { src = edge    + (size_t)n0 * EE + (kt - DD);      stride = EE; }
        else                    { src = timeenc + (size_t)n0 * TT + (kt - DD - EE); stride = TT; }
        int m  = tid >> 3;                     // 32 rows x 8 float4
        int kk = (tid & 7) * 4;
        areg = *(const float4*)(src + (size_t)m * stride + kk);
    };
    auto stsA = [&](int b) {
        const uint32_t Ab = b ? SM_A1 : SM_A0;
        int m  = tid >> 3;
        int kk = (tid & 7) * 4;
        float4 v = areg;
        v.x = clipf(v.x, -50.f, 50.f); v.y = clipf(v.y, -50.f, 50.f);
        v.z = clipf(v.z, -50.f, 50.f); v.w = clipf(v.w, -50.f, 50.f);
        __nv_bfloat162 lo = __float22bfloat162_rn(make_float2(v.x, v.y));
        __nv_bfloat162 hi = __float22bfloat162_rn(make_float2(v.z, v.w));
        uint2 pk;
        pk.x = *(uint32_t*)&lo; pk.y = *(uint32_t*)&hi;
        *(uint2*)(smem + Ab + m * APADB + kk * 2) = pk;
    };
    auto cpB = [&](int c, int b) {
        const int kt = c * BK;
        const uint32_t Bb = sb + (b ? SM_B1 : SM_B0);
        #pragma unroll
        for (int i = 0; i < 8; i++) {
            int id = tid + i * 256;            // 2048 x 16B
            int r  = id >> 2;
            int qt = id & 3;
            const __nv_bfloat16* src = g_Wq_bf16 + (size_t)r * KTOT + kt + qt * 8;
            uint32_t dst = Bb + r * APADB + qt * 16;
            asm volatile("cp.async.ca.shared.global [%0], [%1], 16;\n" :: "r"(dst), "l"(src));
        }
    };
    auto compute = [&](int b) {
        const uint32_t Ab = sb + (b ? SM_A1 : SM_A0);
        const uint32_t Bb = sb + (b ? SM_B1 : SM_B0);
        #pragma unroll
        for (int ks = 0; ks < 2; ks++) {
            uint32_t a[2][4], bf[8][2];
            #pragma unroll
            for (int mt = 0; mt < 2; mt++) {
                uint32_t addr = Ab + (uint32_t)(mt * 16 + (lane & 15)) * APADB
                              + (uint32_t)(ks * 16 + ((lane >> 4) << 3)) * 2;
                ldsm4(a[mt][0], a[mt][1], a[mt][2], a[mt][3], addr);
            }
            #pragma unroll
            for (int pr = 0; pr < 4; pr++) {
                int nb = wid * 64 + pr * 16;
                uint32_t addr = Bb + (uint32_t)(nb + ((lane >> 4) << 3) + (lane & 7)) * APADB
                              + (uint32_t)(ks * 16 + ((lane >> 3) & 1) * 8) * 2;
                ldsm4(bf[2*pr][0], bf[2*pr][1], bf[2*pr+1][0], bf[2*pr+1][1], addr);
            }
            #pragma unroll
            for (int mt = 0; mt < 2; mt++)
                #pragma unroll
                for (int nt = 0; nt < 8; nt++)
                    mma16816(acc[mt][nt], a[mt][0], a[mt][1], a[mt][2], a[mt][3],
                             bf[nt][0], bf[nt][1]);
        }
    };
    // ---- L2 prefetch of epilogue streams, spread over chunks ----
    auto prefetch_slice = [&](int c) {
        int idx = c * 256 + tid;
        const char* pf = nullptr;
        if (idx < 2560)       pf = (const char*)(proto + (size_t)n0 * KK * DD) + (size_t)idx * 128;
        else if (idx < 3072)  pf = (const char*)(raw   + (size_t)n0 * DD)      + (size_t)(idx - 2560) * 128;
        else if (idx < 3200)  pf = (const char*)(timeenc + (size_t)n0 * TT)    + (size_t)(idx - 3072) * 128;
        if (pf) asm volatile("prefetch.global.L2 [%0];" :: "l"(pf));
    };

    // ---- 2-stage pipeline ----
    ldgA(0);
    cpB(0, 0);
    asm volatile("cp.async.commit_group;\n" ::: "memory");
    stsA(0);
    asm volatile("cp.async.wait_group 0;\n" ::: "memory");
    __syncthreads();

    int buf = 0;
    for (int c = 0; c < NCH; c++) {
        if (c < NCH - 1) {
            ldgA(c + 1);
            cpB(c + 1, buf ^ 1);
            asm volatile("cp.async.commit_group;\n" ::: "memory");
        }
        prefetch_slice(c);
        compute(buf);
        if (c < NCH - 1) stsA(buf ^ 1);
        asm volatile("cp.async.wait_group 0;\n" ::: "memory");
        __syncthreads();
        buf ^= 1;
    }

    // ======================= epilogue =======================
    // 1) fragments (+bias) -> xbuf bf16 [32][XSTRIDE] (reuses pipeline smem)
    __nv_bfloat16* xb = (__nv_bfloat16*)smem;
    #pragma unroll
    for (int mt = 0; mt < 2; mt++) {
        #pragma unroll
        for (int nt = 0; nt < 8; nt++) {
            int row = mt * 16 + (lane >> 2);
            int col = wid * 64 + nt * 8 + (lane & 3) * 2;
            float b0 = __ldg(bq + col), b1 = __ldg(bq + col + 1);
            __nv_bfloat162 v0 = __float22bfloat162_rn(
                make_float2(acc[mt][nt][0] + b0, acc[mt][nt][1] + b1));
            __nv_bfloat162 v1 = __float22bfloat162_rn(
                make_float2(acc[mt][nt][2] + b0, acc[mt][nt][3] + b1));
            *(__nv_bfloat162*)&xb[row * XSTRIDE + col]       = v0;
            *(__nv_bfloat162*)&xb[(row + 8) * XSTRIDE + col] = v1;
        }
    }
    __syncthreads();

    // 2) row phase: whole CTA per row; thread owns elems {tid, tid+256}
    float (*red)[16] = (float (*)[16])(smem + SM_RED);

    const float gm0 = gamma[tid],       gm1 = gamma[tid + 256];
    const float bt0 = beta[tid],        bt1 = beta[tid + 256];
    const float w00 = Wg[tid],          w01 = Wg[tid + 256];
    const float w10 = Wg[DD + tid],     w11 = Wg[DD + tid + 256];
    const float w2  = (tid < TT) ? Wg[2 * DD + tid] : 0.f;
    const float bgv  = __ldg(bg);
    const float temp = clipf(__ldg(temperature), 0.5f, 5.0f) + 1e-4f;

    for (int lr = 0; lr < BM; lr++) {
        const int n = n0 + lr;

        // q (pre-LN) from xbuf
        float q0 = __bfloat162float(xb[lr * XSTRIDE + tid]);
        float q1 = __bfloat162float(xb[lr * XSTRIDE + tid + 256]);

        // query LN + tanh
        float st[2] = {q0 + q1, q0 * q0 + q1 * q1};
        block_reduce256<2>(st, red, tid);
        {
            float mu   = st[0] * (1.f / DD);
            float var  = st[1] * (1.f / DD) - mu * mu;
            float rstd = rsqrtf(var + 1e-6f);
            q0 = tanhf((q0 - mu) * rstd * gm0 + bt0);
            q1 = tanhf((q1 - mu) * rstd * gm1 + bt1);
        }

        // raw
        float rv0 = clipf(raw[(size_t)n * DD + tid],       -50.f, 50.f);
        float rv1 = clipf(raw[(size_t)n * DD + tid + 256], -50.f, 50.f);

        // prototypes (single pass, register-resident)
        float p0[KK], p1[KK];
        #pragma unroll
        for (int k = 0; k < KK; k++) {
            const float* pr = proto + ((size_t)n * KK + k) * DD;
            p0[k] = pr[tid];
            p1[k] = pr[tid + 256];
        }

        // norms + dots
        float part[11];
        part[0] = q0 * q0 + q1 * q1;
        #pragma unroll
        for (int k = 0; k < KK; k++) {
            float a0 = clipf(p0[k], -20.f, 20.f);
            float a1 = clipf(p1[k], -20.f, 20.f);
            part[1 + k] = a0 * a0 + a1 * a1;
            part[6 + k] = a0 * q0 + a1 * q1;
        }
        block_reduce256<11>(part, red, tid);

        float qn = fmaxf(sqrtf(part[0]), 1e-6f);
        float sim[KK], mx = -1e30f;
        #pragma unroll
        for (int k = 0; k < KK; k++) {
            float s = part[6 + k] / (qn * fmaxf(sqrtf(part[1 + k]), 1e-6f));
            s = clipf(s, -15.f, 15.f) / temp;
            sim[k] = s; mx = fmaxf(mx, s);
        }
        float denom = 0.f, attn[KK];
        #pragma unroll
        for (int k = 0; k < KK; k++) { attn[k] = expf(sim[k] - mx); denom += attn[k]; }
        float inv = 1.f / denom;
        #pragma unroll
        for (int k = 0; k < KK; k++) attn[k] = clipf(attn[k] * inv, 0.f, 1.f);

        float c0 = attn[0] * p0[0], c1 = attn[0] * p1[0];
        #pragma unroll
        for (int k = 1; k < KK; k++) {
            c0 = fmaf(attn[k], p0[k], c0);
            c1 = fmaf(attn[k], p1[k], c1);
        }
        c0 = clipf(c0, -5.f, 5.f);
        c1 = clipf(c1, -5.f, 5.f);

        // gate
        float gd[1];
        gd[0] = w00 * clipf(rv0, -30.f, 30.f) + w01 * clipf(rv1, -30.f, 30.f)
              + w10 * clipf(c0,  -30.f, 30.f) + w11 * clipf(c1,  -30.f, 30.f);
        if (tid < TT) gd[0] += w2 * clipf(timeenc[(size_t)n * TT + tid], -30.f, 30.f);
        block_reduce256<1>(gd, red, tid);
        float gl = clipf(gd[0] + bgv, -10.f, 10.f);
        float g  = 1.f / (1.f + expf(-gl));

        // residual + final LN
        float u0 = 0.8f * rv0 + 0.2f * ((1.f - g) * rv0 + g * c0);
        float u1 = 0.8f * rv1 + 0.2f * ((1.f - g) * rv1 + g * c1);
        float st2[2] = {u0 + u1, u0 * u0 + u1 * u1};
        block_reduce256<2>(st2, red, tid);
        float mu   = st2[0] * (1.f / DD);
        float var  = st2[1] * (1.f / DD) - mu * mu;
        float rstd = rsqrtf(var + 1e-6f);

        out[(size_t)n * DD + tid]       = clipf((u0 - mu) * rstd * gm0 + bt0, -10.f, 10.f);
        out[(size_t)n * DD + tid + 256] = clipf((u1 - mu) * rstd * gm1 + bt1, -10.f, 10.f);
    }
}

// ---------------------------------------------------------------------------
extern "C" void kernel_launch(void* const* d_in, const int* in_sizes, int n_in,
                              void* d_out, int out_size) {
    const float* raw   = (const float*)d_in[0];
    // d_in[1] = node_features (unused by reference)
    const float* edge  = (const float*)d_in[2];
    const float* timee = (const float*)d_in[3];
    const float* proto = (const float*)d_in[4];
    const float* Wq    = (const float*)d_in[5];
    const float* bq    = (const float*)d_in[6];
    const float* Wg    = (const float*)d_in[7];
    const float* bg    = (const float*)d_in[8];
    const float* gamma = (const float*)d_in[9];
    const float* beta  = (const float*)d_in[10];
    const float* temp  = (const float*)d_in[11];
    float* out = (float*)d_out;

    cudaFuncSetAttribute(fused_kernel, cudaFuncAttributeMaxDynamicSharedMemorySize, SMEM_TOTAL);

    convert_wq<<<(DD * KTOT + 255) / 256, 256>>>(Wq);
    fused_kernel<<<N_ROWS / BM, 256, SMEM_TOTAL>>>(raw, edge, timee, proto, bq,
                                                   Wg, bg, gamma, beta, temp, out);
}

// round 11
// speedup vs baseline: 2.3098x; 2.3098x over previous
#include <cuda_runtime.h>
#include <cuda_bf16.h>
#include <math.h>
#include <stdint.h>

#define N_ROWS 65536
#define DD 512
#define EE 256
#define TT 128
#define KK 5
#define KTOT 896

#define BM 64
#define BN 512
#define BK 32
#define NCH (KTOT / BK)     // 28
#define APADB 80            // bytes per k-row in smem tiles
#define XSTRIDE 520         // xbuf row stride in bf16 elems

// smem (dynamic; xbuf reuses [0, 66560) after mainloop)
#define SM_A0 0u
#define SM_A1 5120u
#define SM_B0 10240u
#define SM_B1 51200u
#define SMEM_TOTAL 92160u

// ---------------- device scratch ----------------
__device__ __align__(16) __nv_bfloat16 g_Wq_bf16[DD * KTOT];   // [512][896] K-major

__device__ __forceinline__ float clipf(float x, float lo, float hi) {
    return fminf(fmaxf(x, lo), hi);
}
__device__ __forceinline__ uint32_t sptr(const void* p) {
    return (uint32_t)__cvta_generic_to_shared(p);
}

__global__ void convert_wq(const float* __restrict__ Wq) {
    int i = blockIdx.x * blockDim.x + threadIdx.x;
    if (i < DD * KTOT) g_Wq_bf16[i] = __float2bfloat16(Wq[i]);
}

__device__ __forceinline__ void mma16816(float c[4], uint32_t a0, uint32_t a1,
                                         uint32_t a2, uint32_t a3,
                                         uint32_t b0, uint32_t b1) {
    asm volatile(
        "mma.sync.aligned.m16n8k16.row.col.f32.bf16.bf16.f32 "
        "{%0,%1,%2,%3}, {%4,%5,%6,%7}, {%8,%9}, {%0,%1,%2,%3};\n"
        : "+f"(c[0]), "+f"(c[1]), "+f"(c[2]), "+f"(c[3])
        : "r"(a0), "r"(a1), "r"(a2), "r"(a3), "r"(b0), "r"(b1));
}
__device__ __forceinline__ void ldsm4(uint32_t& r0, uint32_t& r1, uint32_t& r2,
                                      uint32_t& r3, uint32_t addr) {
    asm volatile("ldmatrix.sync.aligned.m8n8.x4.shared.b16 {%0,%1,%2,%3}, [%4];"
                 : "=r"(r0), "=r"(r1), "=r"(r2), "=r"(r3) : "r"(addr));
}

template <int M>
__device__ __forceinline__ void warp_reduce(float* v) {
    #pragma unroll
    for (int off = 16; off > 0; off >>= 1)
        #pragma unroll
        for (int m = 0; m < M; m++)
            v[m] += __shfl_xor_sync(0xffffffffu, v[m], off);
}

// ---------------------------------------------------------------------------
// Fused: 64x512x896 bf16 HMMA GEMM + LN/tanh + attention + gate + residual + LN
// 256 threads = 8 warps, warp tile 64x64 (n-split).
// Row phase: 8 rows/warp, prototypes register-resident (single DRAM pass).
// Epilogue streams prefetched into L2 during the LAST 13 mainloop chunks.
// ---------------------------------------------------------------------------
__global__ __launch_bounds__(256, 1) void fused_kernel(
    const float* __restrict__ raw,
    const float* __restrict__ edge,
    const float* __restrict__ timeenc,
    const float* __restrict__ proto,
    const float* __restrict__ bq,
    const float* __restrict__ Wg,
    const float* __restrict__ bg,
    const float* __restrict__ gamma,
    const float* __restrict__ beta,
    const float* __restrict__ temperature,
    float* __restrict__ out)
{
    extern __shared__ char smem[];
    const uint32_t sb = sptr(smem);
    const int tid  = threadIdx.x;
    const int lane = tid & 31;
    const int wid  = tid >> 5;
    const int n0   = blockIdx.x * BM;

    float acc[4][8][4];
    #pragma unroll
    for (int mt = 0; mt < 4; mt++)
        #pragma unroll
        for (int nt = 0; nt < 8; nt++)
            #pragma unroll
            for (int j = 0; j < 4; j++) acc[mt][nt][j] = 0.f;

    float4 areg[2];

    auto ldgA = [&](int c) {
        const int kt = c * BK;
        const float* src; int stride;
        if (kt < DD)            { src = raw     + (size_t)n0 * DD + kt;             stride = DD; }
        else if (kt < DD + EE)  { src = edge    + (size_t)n0 * EE + (kt - DD);      stride = EE; }
        else                    { src = timeenc + (size_t)n0 * TT + (kt - DD - EE); stride = TT; }
        #pragma unroll
        for (int i = 0; i < 2; i++) {
            int id = tid + i * 256;            // 512 float4s
            int m  = id >> 3;
            int kk = (id & 7) * 4;
            areg[i] = *(const float4*)(src + (size_t)m * stride + kk);
        }
    };
    auto stsA = [&](int b) {
        const uint32_t Ab = b ? SM_A1 : SM_A0;
        #pragma unroll
        for (int i = 0; i < 2; i++) {
            int id = tid + i * 256;
            int m  = id >> 3;
            int kk = (id & 7) * 4;
            float4 v = areg[i];
            v.x = clipf(v.x, -50.f, 50.f); v.y = clipf(v.y, -50.f, 50.f);
            v.z = clipf(v.z, -50.f, 50.f); v.w = clipf(v.w, -50.f, 50.f);
            __nv_bfloat162 lo = __float22bfloat162_rn(make_float2(v.x, v.y));
            __nv_bfloat162 hi = __float22bfloat162_rn(make_float2(v.z, v.w));
            uint2 pk;
            pk.x = *(uint32_t*)&lo; pk.y = *(uint32_t*)&hi;
            *(uint2*)(smem + Ab + m * APADB + kk * 2) = pk;
        }
    };
    auto cpB = [&](int c, int b) {
        const int kt = c * BK;
        const uint32_t Bb = sb + (b ? SM_B1 : SM_B0);
        #pragma unroll
        for (int i = 0; i < 8; i++) {
            int id = tid + i * 256;            // 2048 x 16B
            int r  = id >> 2;
            int qt = id & 3;
            const __nv_bfloat16* src = g_Wq_bf16 + (size_t)r * KTOT + kt + qt * 8;
            uint32_t dst = Bb + r * APADB + qt * 16;
            asm volatile("cp.async.ca.shared.global [%0], [%1], 16;\n" :: "r"(dst), "l"(src));
        }
    };
    auto compute = [&](int b) {
        const uint32_t Ab = sb + (b ? SM_A1 : SM_A0);
        const uint32_t Bb = sb + (b ? SM_B1 : SM_B0);
        #pragma unroll
        for (int ks = 0; ks < 2; ks++) {
            uint32_t a[4][4], bf[8][2];
            #pragma unroll
            for (int mt = 0; mt < 4; mt++) {
                uint32_t addr = Ab + (uint32_t)(mt * 16 + (lane & 15)) * APADB
                              + (uint32_t)(ks * 16 + ((lane >> 4) << 3)) * 2;
                ldsm4(a[mt][0], a[mt][1], a[mt][2], a[mt][3], addr);
            }
            #pragma unroll
            for (int pr = 0; pr < 4; pr++) {
                int nb = wid * 64 + pr * 16;
                uint32_t addr = Bb + (uint32_t)(nb + ((lane >> 4) << 3) + (lane & 7)) * APADB
                              + (uint32_t)(ks * 16 + ((lane >> 3) & 1) * 8) * 2;
                ldsm4(bf[2*pr][0], bf[2*pr][1], bf[2*pr+1][0], bf[2*pr+1][1], addr);
            }
            #pragma unroll
            for (int mt = 0; mt < 4; mt++)
                #pragma unroll
                for (int nt = 0; nt < 8; nt++)
                    mma16816(acc[mt][nt], a[mt][0], a[mt][1], a[mt][2], a[mt][3],
                             bf[nt][0], bf[nt][1]);
        }
    };
    // ---- L2 prefetch of epilogue streams — LATE window (chunks 15..27) so
    //      lines are still L2-resident when the epilogue consumes them ----
    auto prefetch_slice = [&](int c) {
        if (c < 15) return;
        int base = (c - 15) * 512;
        #pragma unroll
        for (int t = 0; t < 2; t++) {
            int idx = base + tid + t * 256;
            const char* pf = nullptr;
            if (idx < 5120)       pf = (const char*)(proto + (size_t)n0 * KK * DD) + (size_t)idx * 128;
            else if (idx < 6144)  pf = (const char*)(raw   + (size_t)n0 * DD)      + (size_t)(idx - 5120) * 128;
            else if (idx < 6400)  pf = (const char*)(timeenc + (size_t)n0 * TT)    + (size_t)(idx - 6144) * 128;
            if (pf) asm volatile("prefetch.global.L2 [%0];" :: "l"(pf));
        }
    };

    // ---- 2-stage pipeline ----
    ldgA(0);
    cpB(0, 0);
    asm volatile("cp.async.commit_group;\n" ::: "memory");
    stsA(0);
    asm volatile("cp.async.wait_group 0;\n" ::: "memory");
    __syncthreads();

    int buf = 0;
    for (int c = 0; c < NCH; c++) {
        if (c < NCH - 1) {
            ldgA(c + 1);
            cpB(c + 1, buf ^ 1);
            asm volatile("cp.async.commit_group;\n" ::: "memory");
        }
        prefetch_slice(c);
        compute(buf);
        if (c < NCH - 1) stsA(buf ^ 1);
        asm volatile("cp.async.wait_group 0;\n" ::: "memory");
        __syncthreads();
        buf ^= 1;
    }

    // ======================= epilogue =======================
    // 1) fragments (+bias) -> xbuf bf16 [64][XSTRIDE], reusing pipeline smem
    __nv_bfloat16* xb = (__nv_bfloat16*)smem;
    #pragma unroll
    for (int mt = 0; mt < 4; mt++) {
        #pragma unroll
        for (int nt = 0; nt < 8; nt++) {
            int row = mt * 16 + (lane >> 2);
            int col = wid * 64 + nt * 8 + (lane & 3) * 2;
            float b0 = __ldg(bq + col), b1 = __ldg(bq + col + 1);
            __nv_bfloat162 v0 = __float22bfloat162_rn(
                make_float2(acc[mt][nt][0] + b0, acc[mt][nt][1] + b1));
            __nv_bfloat162 v1 = __float22bfloat162_rn(
                make_float2(acc[mt][nt][2] + b0, acc[mt][nt][3] + b1));
            *(__nv_bfloat162*)&xb[row * XSTRIDE + col]       = v0;
            *(__nv_bfloat162*)&xb[(row + 8) * XSTRIDE + col] = v1;
        }
    }
    __syncthreads();

    // 2) row phase: warp w handles rows w*8 .. w*8+7.
    float gmv[16], btv[16], wg0[16], wg1[16], wg2[4];
    #pragma unroll
    for (int j = 0; j < 4; j++) {
        int cc = lane * 4 + j * 128;
        float4 g4 = *(const float4*)(gamma + cc);
        float4 b4 = *(const float4*)(beta + cc);
        float4 w04 = *(const float4*)(Wg + cc);
        float4 w14 = *(const float4*)(Wg + DD + cc);
        gmv[j*4+0]=g4.x; gmv[j*4+1]=g4.y; gmv[j*4+2]=g4.z; gmv[j*4+3]=g4.w;
        btv[j*4+0]=b4.x; btv[j*4+1]=b4.y; btv[j*4+2]=b4.z; btv[j*4+3]=b4.w;
        wg0[j*4+0]=w04.x; wg0[j*4+1]=w04.y; wg0[j*4+2]=w04.z; wg0[j*4+3]=w04.w;
        wg1[j*4+0]=w14.x; wg1[j*4+1]=w14.y; wg1[j*4+2]=w14.z; wg1[j*4+3]=w14.w;
    }
    {
        float4 w24 = *(const float4*)(Wg + 2 * DD + lane * 4);
        wg2[0]=w24.x; wg2[1]=w24.y; wg2[2]=w24.z; wg2[3]=w24.w;
    }
    const float bgv  = __ldg(bg);
    const float temp = clipf(__ldg(temperature), 0.5f, 5.0f) + 1e-4f;

    for (int i = 0; i < 8; i++) {
        const int lr = wid * 8 + i;
        const int n  = n0 + lr;

        // xq -> fp32
        float q[16];
        #pragma unroll
        for (int j = 0; j < 4; j++) {
            uint2 u2 = *(const uint2*)&xb[lr * XSTRIDE + lane * 4 + j * 128];
            __nv_bfloat162 p0 = *(__nv_bfloat162*)&u2.x;
            __nv_bfloat162 p1 = *(__nv_bfloat162*)&u2.y;
            float2 f0 = __bfloat1622float2(p0);
            float2 f1 = __bfloat1622float2(p1);
            q[j*4+0]=f0.x; q[j*4+1]=f0.y; q[j*4+2]=f1.x; q[j*4+3]=f1.y;
        }
        // query LN + tanh
        float st[2] = {0.f, 0.f};
        #pragma unroll
        for (int e = 0; e < 16; e++) { st[0] += q[e]; st[1] += q[e]*q[e]; }
        warp_reduce<2>(st);
        {
            float mu   = st[0] * (1.f / DD);
            float var  = st[1] * (1.f / DD) - mu * mu;
            float rstd = rsqrtf(var + 1e-6f);
            #pragma unroll
            for (int e = 0; e < 16; e++)
                q[e] = tanhf((q[e] - mu) * rstd * gmv[e] + btv[e]);
        }
        // raw (clipped)
        float rv[16];
        #pragma unroll
        for (int j = 0; j < 4; j++) {
            float4 r4 = *(const float4*)(raw + (size_t)n * DD + lane * 4 + j * 128);
            rv[j*4+0]=clipf(r4.x,-50.f,50.f); rv[j*4+1]=clipf(r4.y,-50.f,50.f);
            rv[j*4+2]=clipf(r4.z,-50.f,50.f); rv[j*4+3]=clipf(r4.w,-50.f,50.f);
        }
        // ---- prototypes: load ONCE into registers ----
        float p[KK][16];
        #pragma unroll
        for (int k = 0; k < KK; k++) {
            const float* pr = proto + ((size_t)n * KK + k) * DD;
            #pragma unroll
            for (int j = 0; j < 4; j++) {
                float4 p4 = *(const float4*)(pr + lane * 4 + j * 128);
                p[k][j*4+0]=p4.x; p[k][j*4+1]=p4.y; p[k][j*4+2]=p4.z; p[k][j*4+3]=p4.w;
            }
        }
        // norms + dots (clipped view of p)
        float part[11];
        {
            float qss = 0.f;
            #pragma unroll
            for (int e = 0; e < 16; e++) qss += q[e]*q[e];
            part[0] = qss;
        }
        #pragma unroll
        for (int k = 0; k < KK; k++) {
            float pss = 0.f, pdot = 0.f;
            #pragma unroll
            for (int e = 0; e < 16; e++) {
                float ps = clipf(p[k][e], -20.f, 20.f);
                pss  = fmaf(ps, ps, pss);
                pdot = fmaf(ps, q[e], pdot);
            }
            part[1 + k] = pss;
            part[6 + k] = pdot;
        }
        warp_reduce<11>(part);

        float qn = fmaxf(sqrtf(part[0]), 1e-6f);
        float sim[KK], mx = -1e30f;
        #pragma unroll
        for (int k = 0; k < KK; k++) {
            float s = part[6 + k] / (qn * fmaxf(sqrtf(part[1 + k]), 1e-6f));
            s = clipf(s, -15.f, 15.f) / temp;
            sim[k] = s; mx = fmaxf(mx, s);
        }
        float denom = 0.f, attn[KK];
        #pragma unroll
        for (int k = 0; k < KK; k++) { attn[k] = expf(sim[k] - mx); denom += attn[k]; }
        float inv = 1.f / denom;
        #pragma unroll
        for (int k = 0; k < KK; k++) attn[k] = clipf(attn[k] * inv, 0.f, 1.f);

        // candidate from register-resident (unclipped) protos, clip +-5
        float cand[16];
        #pragma unroll
        for (int e = 0; e < 16; e++) {
            float cc = attn[0] * p[0][e];
            #pragma unroll
            for (int k = 1; k < KK; k++) cc = fmaf(attn[k], p[k][e], cc);
            cand[e] = clipf(cc, -5.f, 5.f);
        }

        // gate
        float gd[1] = {0.f};
        #pragma unroll
        for (int e = 0; e < 16; e++) {
            gd[0] += wg0[e] * clipf(rv[e],  -30.f, 30.f);
            gd[0] += wg1[e] * clipf(cand[e],-30.f, 30.f);
        }
        {
            float4 t4 = *(const float4*)(timeenc + (size_t)n * TT + lane * 4);
            gd[0] += wg2[0]*clipf(t4.x,-30.f,30.f) + wg2[1]*clipf(t4.y,-30.f,30.f)
                   + wg2[2]*clipf(t4.z,-30.f,30.f) + wg2[3]*clipf(t4.w,-30.f,30.f);
        }
        warp_reduce<1>(gd);
        float gl = clipf(gd[0] + bgv, -10.f, 10.f);
        float g  = 1.f / (1.f + expf(-gl));

        // residual + final LN
        float u[16], st2[2] = {0.f, 0.f};
        #pragma unroll
        for (int e = 0; e < 16; e++) {
            u[e] = 0.8f * rv[e] + 0.2f * ((1.f - g) * rv[e] + g * cand[e]);
            st2[0] += u[e]; st2[1] += u[e]*u[e];
        }
        warp_reduce<2>(st2);
        float mu   = st2[0] * (1.f / DD);
        float var  = st2[1] * (1.f / DD) - mu * mu;
        float rstd = rsqrtf(var + 1e-6f);
        #pragma unroll
        for (int j = 0; j < 4; j++) {
            float4 o;
            o.x = clipf((u[j*4+0]-mu)*rstd*gmv[j*4+0]+btv[j*4+0], -10.f, 10.f);
            o.y = clipf((u[j*4+1]-mu)*rstd*gmv[j*4+1]+btv[j*4+1], -10.f, 10.f);
            o.z = clipf((u[j*4+2]-mu)*rstd*gmv[j*4+2]+btv[j*4+2], -10.f, 10.f);
            o.w = clipf((u[j*4+3]-mu)*rstd*gmv[j*4+3]+btv[j*4+3], -10.f, 10.f);
            *(float4*)(out + (size_t)n * DD + lane * 4 + j * 128) = o;
        }
    }
}

// ---------------------------------------------------------------------------
extern "C" void kernel_launch(void* const* d_in, const int* in_sizes, int n_in,
                              void* d_out, int out_size) {
    const float* raw   = (const float*)d_in[0];
    // d_in[1] = node_features (unused by reference)
    const float* edge  = (const float*)d_in[2];
    const float* timee = (const float*)d_in[3];
    const float* proto = (const float*)d_in[4];
    const float* Wq    = (const float*)d_in[5];
    const float* bq    = (const float*)d_in[6];
    const float* Wg    = (const float*)d_in[7];
    const float* bg    = (const float*)d_in[8];
    const float* gamma = (const float*)d_in[9];
    const float* beta  = (const float*)d_in[10];
    const float* temp  = (const float*)d_in[11];
    float* out = (float*)d_out;

    cudaFuncSetAttribute(fused_kernel, cudaFuncAttributeMaxDynamicSharedMemorySize, SMEM_TOTAL);

    convert_wq<<<(DD * KTOT + 255) / 256, 256>>>(Wq);
    fused_kernel<<<N_ROWS / BM, 256, SMEM_TOTAL>>>(raw, edge, timee, proto, bq,
                                                   Wg, bg, gamma, beta, temp, out);
}

// round 12
// speedup vs baseline: 2.6925x; 1.1657x over previous
#include <cuda_runtime.h>
#include <cuda_bf16.h>
#include <math.h>
#include <stdint.h>

#define N_ROWS 65536
#define DD 512
#define EE 256
#define TT 128
#define KK 5
#define KTOT 896

#define BM 64
#define BN 512
#define BK 64
#define NCH (KTOT / BK)     // 14
#define APADB 144           // bytes per k-row in smem tiles (128B data + 16B pad)
#define XSTRIDE 520         // xbuf row stride in bf16 elems

// smem: A 2 x 9216 | B 2 x 73728  (xbuf reuses [0, 66560) after mainloop)
#define SM_A0 0u
#define SM_A1 9216u
#define SM_B0 18432u
#define SM_B1 92160u
#define SMEM_TOTAL 165888u

// ---------------- device scratch ----------------
__device__ __align__(16) __nv_bfloat16 g_Wq_bf16[DD * KTOT];   // [512][896] K-major

__device__ __forceinline__ float clipf(float x, float lo, float hi) {
    return fminf(fmaxf(x, lo), hi);
}
__device__ __forceinline__ uint32_t sptr(const void* p) {
    return (uint32_t)__cvta_generic_to_shared(p);
}

__global__ void convert_wq(const float* __restrict__ Wq) {
    int i = blockIdx.x * blockDim.x + threadIdx.x;
    if (i < DD * KTOT) g_Wq_bf16[i] = __float2bfloat16(Wq[i]);
}

__device__ __forceinline__ void mma16816(float c[4], uint32_t a0, uint32_t a1,
                                         uint32_t a2, uint32_t a3,
                                         uint32_t b0, uint32_t b1) {
    asm volatile(
        "mma.sync.aligned.m16n8k16.row.col.f32.bf16.bf16.f32 "
        "{%0,%1,%2,%3}, {%4,%5,%6,%7}, {%8,%9}, {%0,%1,%2,%3};\n"
        : "+f"(c[0]), "+f"(c[1]), "+f"(c[2]), "+f"(c[3])
        : "r"(a0), "r"(a1), "r"(a2), "r"(a3), "r"(b0), "r"(b1));
}
__device__ __forceinline__ void ldsm4(uint32_t& r0, uint32_t& r1, uint32_t& r2,
                                      uint32_t& r3, uint32_t addr) {
    asm volatile("ldmatrix.sync.aligned.m8n8.x4.shared.b16 {%0,%1,%2,%3}, [%4];"
                 : "=r"(r0), "=r"(r1), "=r"(r2), "=r"(r3) : "r"(addr));
}

template <int M>
__device__ __forceinline__ void warp_reduce(float* v) {
    #pragma unroll
    for (int off = 16; off > 0; off >>= 1)
        #pragma unroll
        for (int m = 0; m < M; m++)
            v[m] += __shfl_xor_sync(0xffffffffu, v[m], off);
}

// ---------------------------------------------------------------------------
// Fused: 64x512x896 bf16 HMMA GEMM (BK=64, 14 chunks) + LN/tanh + attention +
// gate + residual + LN. 256 threads = 8 warps, warp tile 64x64 (n-split).
// Row phase: 8 rows/warp, prototypes register-resident (single DRAM pass).
// ---------------------------------------------------------------------------
__global__ __launch_bounds__(256, 1) void fused_kernel(
    const float* __restrict__ raw,
    const float* __restrict__ edge,
    const float* __restrict__ timeenc,
    const float* __restrict__ proto,
    const float* __restrict__ bq,
    const float* __restrict__ Wg,
    const float* __restrict__ bg,
    const float* __restrict__ gamma,
    const float* __restrict__ beta,
    const float* __restrict__ temperature,
    float* __restrict__ out)
{
    extern __shared__ char smem[];
    const uint32_t sb = sptr(smem);
    const int tid  = threadIdx.x;
    const int lane = tid & 31;
    const int wid  = tid >> 5;
    const int n0   = blockIdx.x * BM;

    float acc[4][8][4];
    #pragma unroll
    for (int mt = 0; mt < 4; mt++)
        #pragma unroll
        for (int nt = 0; nt < 8; nt++)
            #pragma unroll
            for (int j = 0; j < 4; j++) acc[mt][nt][j] = 0.f;

    float4 areg[4];

    // ---- A: LDG fp32 chunk (64 rows x 64 k) -> 4 float4/thread ----
    auto ldgA = [&](int c) {
        const int kt = c * BK;
        const float* src; int stride;
        if (kt < DD)            { src = raw     + (size_t)n0 * DD + kt;             stride = DD; }
        else if (kt < DD + EE)  { src = edge    + (size_t)n0 * EE + (kt - DD);      stride = EE; }
        else                    { src = timeenc + (size_t)n0 * TT + (kt - DD - EE); stride = TT; }
        #pragma unroll
        for (int i = 0; i < 4; i++) {
            int id = tid + i * 256;            // 1024 float4s (16 per row)
            int m  = id >> 4;
            int kk = (id & 15) * 4;
            areg[i] = *(const float4*)(src + (size_t)m * stride + kk);
        }
    };
    auto stsA = [&](int b) {
        const uint32_t Ab = b ? SM_A1 : SM_A0;
        #pragma unroll
        for (int i = 0; i < 4; i++) {
            int id = tid + i * 256;
            int m  = id >> 4;
            int kk = (id & 15) * 4;
            float4 v = areg[i];
            v.x = clipf(v.x, -50.f, 50.f); v.y = clipf(v.y, -50.f, 50.f);
            v.z = clipf(v.z, -50.f, 50.f); v.w = clipf(v.w, -50.f, 50.f);
            __nv_bfloat162 lo = __float22bfloat162_rn(make_float2(v.x, v.y));
            __nv_bfloat162 hi = __float22bfloat162_rn(make_float2(v.z, v.w));
            uint2 pk;
            pk.x = *(uint32_t*)&lo; pk.y = *(uint32_t*)&hi;
            *(uint2*)(smem + Ab + m * APADB + kk * 2) = pk;
        }
    };
    // ---- B: cp.async chunk (512 rows x 64 k bf16 = 64KB), 16 x 16B/thread ----
    auto cpB = [&](int c, int b) {
        const int kt = c * BK;
        const uint32_t Bb = sb + (b ? SM_B1 : SM_B0);
        #pragma unroll
        for (int i = 0; i < 16; i++) {
            int id = tid + i * 256;            // 4096 x 16B (8 per row)
            int r  = id >> 3;
            int qt = id & 7;
            const __nv_bfloat16* src = g_Wq_bf16 + (size_t)r * KTOT + kt + qt * 8;
            uint32_t dst = Bb + r * APADB + qt * 16;
            asm volatile("cp.async.ca.shared.global [%0], [%1], 16;\n" :: "r"(dst), "l"(src));
        }
    };
    auto compute = [&](int b) {
        const uint32_t Ab = sb + (b ? SM_A1 : SM_A0);
        const uint32_t Bb = sb + (b ? SM_B1 : SM_B0);
        #pragma unroll
        for (int ks = 0; ks < 4; ks++) {
            uint32_t a[4][4], bf[8][2];
            #pragma unroll
            for (int mt = 0; mt < 4; mt++) {
                uint32_t addr = Ab + (uint32_t)(mt * 16 + (lane & 15)) * APADB
                              + (uint32_t)(ks * 16 + ((lane >> 4) << 3)) * 2;
                ldsm4(a[mt][0], a[mt][1], a[mt][2], a[mt][3], addr);
            }
            #pragma unroll
            for (int pr = 0; pr < 4; pr++) {
                int nb = wid * 64 + pr * 16;
                uint32_t addr = Bb + (uint32_t)(nb + ((lane >> 4) << 3) + (lane & 7)) * APADB
                              + (uint32_t)(ks * 16 + ((lane >> 3) & 1) * 8) * 2;
                ldsm4(bf[2*pr][0], bf[2*pr][1], bf[2*pr+1][0], bf[2*pr+1][1], addr);
            }
            #pragma unroll
            for (int mt = 0; mt < 4; mt++)
                #pragma unroll
                for (int nt = 0; nt < 8; nt++)
                    mma16816(acc[mt][nt], a[mt][0], a[mt][1], a[mt][2], a[mt][3],
                             bf[nt][0], bf[nt][1]);
        }
    };
    // ---- L2 prefetch of epilogue streams, spread over chunks (early, as R7) ----
    auto prefetch_slice = [&](int c) {
        int base = c * 512;
        #pragma unroll
        for (int t = 0; t < 2; t++) {
            int idx = base + tid + t * 256;
            const char* pf = nullptr;
            if (idx < 5120)       pf = (const char*)(proto + (size_t)n0 * KK * DD) + (size_t)idx * 128;
            else if (idx < 6144)  pf = (const char*)(raw   + (size_t)n0 * DD)      + (size_t)(idx - 5120) * 128;
            else if (idx < 6400)  pf = (const char*)(timeenc + (size_t)n0 * TT)    + (size_t)(idx - 6144) * 128;
            if (pf) asm volatile("prefetch.global.L2 [%0];" :: "l"(pf));
        }
    };

    // ---- 2-stage pipeline ----
    ldgA(0);
    cpB(0, 0);
    asm volatile("cp.async.commit_group;\n" ::: "memory");
    stsA(0);
    asm volatile("cp.async.wait_group 0;\n" ::: "memory");
    __syncthreads();

    int buf = 0;
    for (int c = 0; c < NCH; c++) {
        if (c < NCH - 1) {
            ldgA(c + 1);
            cpB(c + 1, buf ^ 1);
            asm volatile("cp.async.commit_group;\n" ::: "memory");
        }
        prefetch_slice(c);
        compute(buf);
        if (c < NCH - 1) stsA(buf ^ 1);
        asm volatile("cp.async.wait_group 0;\n" ::: "memory");
        __syncthreads();
        buf ^= 1;
    }

    // ======================= epilogue =======================
    // 1) fragments (+bias) -> xbuf bf16 [64][XSTRIDE], reusing pipeline smem
    __nv_bfloat16* xb = (__nv_bfloat16*)smem;
    #pragma unroll
    for (int mt = 0; mt < 4; mt++) {
        #pragma unroll
        for (int nt = 0; nt < 8; nt++) {
            int row = mt * 16 + (lane >> 2);
            int col = wid * 64 + nt * 8 + (lane & 3) * 2;
            float b0 = __ldg(bq + col), b1 = __ldg(bq + col + 1);
            __nv_bfloat162 v0 = __float22bfloat162_rn(
                make_float2(acc[mt][nt][0] + b0, acc[mt][nt][1] + b1));
            __nv_bfloat162 v1 = __float22bfloat162_rn(
                make_float2(acc[mt][nt][2] + b0, acc[mt][nt][3] + b1));
            *(__nv_bfloat162*)&xb[row * XSTRIDE + col]       = v0;
            *(__nv_bfloat162*)&xb[(row + 8) * XSTRIDE + col] = v1;
        }
    }
    __syncthreads();

    // 2) row phase: warp w handles rows w*8 .. w*8+7.
    float gmv[16], btv[16], wg0[16], wg1[16], wg2[4];
    #pragma unroll
    for (int j = 0; j < 4; j++) {
        int cc = lane * 4 + j * 128;
        float4 g4 = *(const float4*)(gamma + cc);
        float4 b4 = *(const float4*)(beta + cc);
        float4 w04 = *(const float4*)(Wg + cc);
        float4 w14 = *(const float4*)(Wg + DD + cc);
        gmv[j*4+0]=g4.x; gmv[j*4+1]=g4.y; gmv[j*4+2]=g4.z; gmv[j*4+3]=g4.w;
        btv[j*4+0]=b4.x; btv[j*4+1]=b4.y; btv[j*4+2]=b4.z; btv[j*4+3]=b4.w;
        wg0[j*4+0]=w04.x; wg0[j*4+1]=w04.y; wg0[j*4+2]=w04.z; wg0[j*4+3]=w04.w;
        wg1[j*4+0]=w14.x; wg1[j*4+1]=w14.y; wg1[j*4+2]=w14.z; wg1[j*4+3]=w14.w;
    }
    {
        float4 w24 = *(const float4*)(Wg + 2 * DD + lane * 4);
        wg2[0]=w24.x; wg2[1]=w24.y; wg2[2]=w24.z; wg2[3]=w24.w;
    }
    const float bgv  = __ldg(bg);
    const float temp = clipf(__ldg(temperature), 0.5f, 5.0f) + 1e-4f;

    for (int i = 0; i < 8; i++) {
        const int lr = wid * 8 + i;
        const int n  = n0 + lr;

        // xq -> fp32
        float q[16];
        #pragma unroll
        for (int j = 0; j < 4; j++) {
            uint2 u2 = *(const uint2*)&xb[lr * XSTRIDE + lane * 4 + j * 128];
            __nv_bfloat162 p0 = *(__nv_bfloat162*)&u2.x;
            __nv_bfloat162 p1 = *(__nv_bfloat162*)&u2.y;
            float2 f0 = __bfloat1622float2(p0);
            float2 f1 = __bfloat1622float2(p1);
            q[j*4+0]=f0.x; q[j*4+1]=f0.y; q[j*4+2]=f1.x; q[j*4+3]=f1.y;
        }
        // query LN + tanh
        float st[2] = {0.f, 0.f};
        #pragma unroll
        for (int e = 0; e < 16; e++) { st[0] += q[e]; st[1] += q[e]*q[e]; }
        warp_reduce<2>(st);
        {
            float mu   = st[0] * (1.f / DD);
            float var  = st[1] * (1.f / DD) - mu * mu;
            float rstd = rsqrtf(var + 1e-6f);
            #pragma unroll
            for (int e = 0; e < 16; e++)
                q[e] = tanhf((q[e] - mu) * rstd * gmv[e] + btv[e]);
        }
        // raw (clipped)
        float rv[16];
        #pragma unroll
        for (int j = 0; j < 4; j++) {
            float4 r4 = *(const float4*)(raw + (size_t)n * DD + lane * 4 + j * 128);
            rv[j*4+0]=clipf(r4.x,-50.f,50.f); rv[j*4+1]=clipf(r4.y,-50.f,50.f);
            rv[j*4+2]=clipf(r4.z,-50.f,50.f); rv[j*4+3]=clipf(r4.w,-50.f,50.f);
        }
        // ---- prototypes: load ONCE into registers ----
        float p[KK][16];
        #pragma unroll
        for (int k = 0; k < KK; k++) {
            const float* pr = proto + ((size_t)n * KK + k) * DD;
            #pragma unroll
            for (int j = 0; j < 4; j++) {
                float4 p4 = *(const float4*)(pr + lane * 4 + j * 128);
                p[k][j*4+0]=p4.x; p[k][j*4+1]=p4.y; p[k][j*4+2]=p4.z; p[k][j*4+3]=p4.w;
            }
        }
        // norms + dots (clipped view of p)
        float part[11];
        {
            float qss = 0.f;
            #pragma unroll
            for (int e = 0; e < 16; e++) qss += q[e]*q[e];
            part[0] = qss;
        }
        #pragma unroll
        for (int k = 0; k < KK; k++) {
            float pss = 0.f, pdot = 0.f;
            #pragma unroll
            for (int e = 0; e < 16; e++) {
                float ps = clipf(p[k][e], -20.f, 20.f);
                pss  = fmaf(ps, ps, pss);
                pdot = fmaf(ps, q[e], pdot);
            }
            part[1 + k] = pss;
            part[6 + k] = pdot;
        }
        warp_reduce<11>(part);

        float qn = fmaxf(sqrtf(part[0]), 1e-6f);
        float sim[KK], mx = -1e30f;
        #pragma unroll
        for (int k = 0; k < KK; k++) {
            float s = part[6 + k] / (qn * fmaxf(sqrtf(part[1 + k]), 1e-6f));
            s = clipf(s, -15.f, 15.f) / temp;
            sim[k] = s; mx = fmaxf(mx, s);
        }
        float denom = 0.f, attn[KK];
        #pragma unroll
        for (int k = 0; k < KK; k++) { attn[k] = expf(sim[k] - mx); denom += attn[k]; }
        float inv = 1.f / denom;
        #pragma unroll
        for (int k = 0; k < KK; k++) attn[k] = clipf(attn[k] * inv, 0.f, 1.f);

        // candidate from register-resident (unclipped) protos, clip +-5
        float cand[16];
        #pragma unroll
        for (int e = 0; e < 16; e++) {
            float cc = attn[0] * p[0][e];
            #pragma unroll
            for (int k = 1; k < KK; k++) cc = fmaf(attn[k], p[k][e], cc);
            cand[e] = clipf(cc, -5.f, 5.f);
        }

        // gate
        float gd[1] = {0.f};
        #pragma unroll
        for (int e = 0; e < 16; e++) {
            gd[0] += wg0[e] * clipf(rv[e],  -30.f, 30.f);
            gd[0] += wg1[e] * clipf(cand[e],-30.f, 30.f);
        }
        {
            float4 t4 = *(const float4*)(timeenc + (size_t)n * TT + lane * 4);
            gd[0] += wg2[0]*clipf(t4.x,-30.f,30.f) + wg2[1]*clipf(t4.y,-30.f,30.f)
                   + wg2[2]*clipf(t4.z,-30.f,30.f) + wg2[3]*clipf(t4.w,-30.f,30.f);
        }
        warp_reduce<1>(gd);
        float gl = clipf(gd[0] + bgv, -10.f, 10.f);
        float g  = 1.f / (1.f + expf(-gl));

        // residual + final LN
        float u[16], st2[2] = {0.f, 0.f};
        #pragma unroll
        for (int e = 0; e < 16; e++) {
            u[e] = 0.8f * rv[e] + 0.2f * ((1.f - g) * rv[e] + g * cand[e]);
            st2[0] += u[e]; st2[1] += u[e]*u[e];
        }
        warp_reduce<2>(st2);
        float mu   = st2[0] * (1.f / DD);
        float var  = st2[1] * (1.f / DD) - mu * mu;
        float rstd = rsqrtf(var + 1e-6f);
        #pragma unroll
        for (int j = 0; j < 4; j++) {
            float4 o;
            o.x = clipf((u[j*4+0]-mu)*rstd*gmv[j*4+0]+btv[j*4+0], -10.f, 10.f);
            o.y = clipf((u[j*4+1]-mu)*rstd*gmv[j*4+1]+btv[j*4+1], -10.f, 10.f);
            o.z = clipf((u[j*4+2]-mu)*rstd*gmv[j*4+2]+btv[j*4+2], -10.f, 10.f);
            o.w = clipf((u[j*4+3]-mu)*rstd*gmv[j*4+3]+btv[j*4+3], -10.f, 10.f);
            *(float4*)(out + (size_t)n * DD + lane * 4 + j * 128) = o;
        }
    }
}

// ---------------------------------------------------------------------------
extern "C" void kernel_launch(void* const* d_in, const int* in_sizes, int n_in,
                              void* d_out, int out_size) {
    const float* raw   = (const float*)d_in[0];
    // d_in[1] = node_features (unused by reference)
    const float* edge  = (const float*)d_in[2];
    const float* timee = (const float*)d_in[3];
    const float* proto = (const float*)d_in[4];
    const float* Wq    = (const float*)d_in[5];
    const float* bq    = (const float*)d_in[6];
    const float* Wg    = (const float*)d_in[7];
    const float* bg    = (const float*)d_in[8];
    const float* gamma = (const float*)d_in[9];
    const float* beta  = (const float*)d_in[10];
    const float* temp  = (const float*)d_in[11];
    float* out = (float*)d_out;

    cudaFuncSetAttribute(fused_kernel, cudaFuncAttributeMaxDynamicSharedMemorySize, SMEM_TOTAL);

    convert_wq<<<(DD * KTOT + 255) / 256, 256>>>(Wq);
    fused_kernel<<<N_ROWS / BM, 256, SMEM_TOTAL>>>(raw, edge, timee, proto, bq,
                                                   Wg, bg, gamma, beta, temp, out);
}